// round 11
// baseline (speedup 1.0000x reference)
#include <cuda_runtime.h>
#include <cuda_bf16.h>
#include <cstdint>

#define DINL __device__ __forceinline__

// ---------------- K1 smem layout (bytes), per 128-thread CTA ----------------
constexpr int SM_BIAS  = 0;            // 800 floats (b1|b2|b3|b4)
constexpr int SM_W2    = 3200;         // 32 rows x stride 576
constexpr int SM_W3    = 21632;        // 128 rows x stride 192
constexpr int SM_NOISE = 46208;        // 64 rows x stride 144
constexpr int SM_BUF   = 55424;        // 2 x 24576 double buffer (W1 chunks)
constexpr int SM_BUFS  = 24576;
constexpr int SM_TOTAL = SM_BUF + 2 * SM_BUFS;   // 104576 -> 2 CTAs/SM

// ---------------- K2 smem layout ----------------
constexpr int K2_D   = 0;                  // 64 rows x 576
constexpr int K2_W   = 36864;              // 128 rows x 576
constexpr int K2_TOTAL = K2_W + 128 * 576; // 110592 -> 2 CTAs/SM

// ---------------- global scratch ----------------
// weight frags: W1 chunk-major [16 chunks of 32k][128 rows][128B]; others row-major
__device__ __align__(256) unsigned char gW1[16 * 128 * 128];
__device__ __align__(256) unsigned char gW2[32 * 512];
__device__ __align__(256) unsigned char gW3[128 * 128];
__device__ __align__(256) unsigned char gW4[512 * 512];
// d activations in A-frag layout: [131072 rows][512B]
__device__ __align__(256) unsigned char g_dfrag[(size_t)131072 * 512];

DINL void mma16816(float c[4], uint32_t a0, uint32_t a1, uint32_t a2, uint32_t a3,
                   uint32_t b0, uint32_t b1) {
    asm volatile("mma.sync.aligned.m16n8k16.row.col.f32.bf16.bf16.f32 "
        "{%0,%1,%2,%3}, {%4,%5,%6,%7}, {%8,%9}, {%0,%1,%2,%3};"
        : "+f"(c[0]), "+f"(c[1]), "+f"(c[2]), "+f"(c[3])
        : "r"(a0), "r"(a1), "r"(a2), "r"(a3), "r"(b0), "r"(b1));
}

DINL void split2(float a, float b, uint32_t& h, uint32_t& l) {
    __nv_bfloat16 ha = __float2bfloat16(a), hb = __float2bfloat16(b);
    __nv_bfloat16 la = __float2bfloat16(a - __bfloat162float(ha));
    __nv_bfloat16 lb = __float2bfloat16(b - __bfloat162float(hb));
    h = ((uint32_t)__bfloat16_as_ushort(hb) << 16) | (uint32_t)__bfloat16_as_ushort(ha);
    l = ((uint32_t)__bfloat16_as_ushort(lb) << 16) | (uint32_t)__bfloat16_as_ushort(la);
}

// 16B frag slot at (kb,q): {h(k0,k0+1)}@0, {h(k0+8,k0+9)}@4, {l(k0..)}@8, {l(k0+8..)}@12
DINL void frag_store(unsigned char* p, float4 v) {
    uint32_t h0, l0, h1, l1;
    split2(v.x, v.y, h0, l0);
    split2(v.z, v.w, h1, l1);
    *(uint32_t*)(p)      = h0;
    *(uint32_t*)(p + 8)  = l0;
    *(uint32_t*)(p + 16) = h1;
    *(uint32_t*)(p + 24) = l1;
}

// ---------------- setup kernel: convert weights to fragment layout ----------------
__global__ void __launch_bounds__(256) setup_kernel(
    const float* __restrict__ W1, const float* __restrict__ W2,
    const float* __restrict__ W3, const float* __restrict__ W4)
{
    int i = blockIdx.x * 256 + threadIdx.x;
    if (i < 16384) {                       // W1 [128 x 512], 32k-chunk-major dst
        int r = i >> 7, k = (i & 127) << 2;
        float4 v = __ldg((const float4*)(W1 + (size_t)r * 512 + k));
        int c = k >> 5, kb = (k >> 4) & 1, q = (k & 7) >> 1, sub = ((k >> 3) & 1) << 2;
        frag_store(gW1 + c * 16384 + r * 128 + kb * 64 + q * 16 + sub, v);
    } else if (i < 32768) {                // W4 [512 x 128]
        int j = i - 16384;
        int r = j >> 5, k = (j & 31) << 2;
        float4 v = __ldg((const float4*)(W4 + (size_t)r * 128 + k));
        int kb = k >> 4, q = (k & 7) >> 1, sub = ((k >> 3) & 1) << 2;
        frag_store(gW4 + r * 512 + kb * 64 + q * 16 + sub, v);
    } else if (i < 33792) {                // W2 [32 x 128]
        int j = i - 32768;
        int r = j >> 5, k = (j & 31) << 2;
        float4 v = __ldg((const float4*)(W2 + (size_t)r * 128 + k));
        int kb = k >> 4, q = (k & 7) >> 1, sub = ((k >> 3) & 1) << 2;
        frag_store(gW2 + r * 512 + kb * 64 + q * 16 + sub, v);
    } else if (i < 34816) {                // W3 [128 x 32]
        int j = i - 33792;
        int r = j >> 3, k = (j & 7) << 2;
        float4 v = __ldg((const float4*)(W3 + (size_t)r * 32 + k));
        int kb = k >> 4, q = (k & 7) >> 1, sub = ((k >> 3) & 1) << 2;
        frag_store(gW3 + r * 128 + kb * 64 + q * 16 + sub, v);
    }
}

// ---------------- cp.async helpers ----------------
DINL void cpa16(uint32_t sdst, const void* gsrc) {
    asm volatile("cp.async.cg.shared.global [%0], [%1], 16;"
                 :: "r"(sdst), "l"(gsrc) : "memory");
}
#define CPCOMMIT() asm volatile("cp.async.commit_group;" ::: "memory")
#define CPWAIT1()  asm volatile("cp.async.wait_group 1;" ::: "memory")
#define CPWAIT0()  asm volatile("cp.async.wait_group 0;" ::: "memory")

DINL uint32_t smem_u32(const void* p) {
    uint32_t a;
    asm("{ .reg .u64 t; cvta.to.shared.u64 t, %1; cvt.u32.u64 %0, t; }" : "=r"(a) : "l"(p));
    return a;
}

// copy ROWS x (IPR*16B) contiguous gmem -> smem rows with padded stride RSD (128 thr)
template<int ROWS, int IPR, int RSD>
DINL void cppad(uint32_t sdst, const unsigned char* __restrict__ gsrc, int t) {
    constexpr int TOT = ROWS * IPR;
    #pragma unroll
    for (int i = t; i < TOT; i += 128) {
        int r = i / IPR, ii = i - r * IPR;
        cpa16(sdst + r * RSD + ii * 16, gsrc + (size_t)i * 16);
    }
}

// one 16-k step, A regs, B smem (stride RSB), NJ n-tiles, 3-pass hi/lo
template<int NJ, int RSB>
DINL void gemm_step_r(const char* smc, const uint32_t ah[4], const uint32_t al[4],
                      int boff, int g, int q, float (*acc)[4]) {
    #pragma unroll
    for (int j = 0; j < NJ; j++) {
        uint4 vb = *(const uint4*)(smc + boff + (size_t)(j * 8 + g) * RSB + q * 16);
        mma16816(acc[j], ah[0], ah[1], ah[2], ah[3], vb.x, vb.y);
        mma16816(acc[j], ah[0], ah[1], ah[2], ah[3], vb.z, vb.w);
        mma16816(acc[j], al[0], al[1], al[2], al[3], vb.x, vb.y);
    }
}

DINL void loadx(const float* __restrict__ xrow, int c, float2 xf[8], int q) {
    const float* p0 = xrow;
    const float* p1 = xrow + 8 * 512;
    #pragma unroll
    for (int kb = 0; kb < 2; kb++) {
        int k0 = c * 32 + kb * 16 + q * 2;
        xf[kb * 4 + 0] = __ldg((const float2*)(p0 + k0));
        xf[kb * 4 + 1] = __ldg((const float2*)(p1 + k0));
        xf[kb * 4 + 2] = __ldg((const float2*)(p0 + k0 + 8));
        xf[kb * 4 + 3] = __ldg((const float2*)(p1 + k0 + 8));
    }
}

DINL void compute_chunk1(const char* smc, int buf, const float2 xf[8],
                         int g, int q, float (*acc)[4]) {
    #pragma unroll
    for (int kb = 0; kb < 2; kb++) {
        uint32_t ah[4], al[4];
        #pragma unroll
        for (int s = 0; s < 4; s++)
            split2(xf[kb * 4 + s].x, xf[kb * 4 + s].y, ah[s], al[s]);
        gemm_step_r<16, 192>(smc, ah, al, buf + kb * 64, g, q, acc);
    }
}

// =============== K1: GEMM1 + GEMM2 + channel + GEMM3, writes d-frags ===============
__global__ void __launch_bounds__(128, 2) channel_net_k1(
    const float* __restrict__ x, const float* __restrict__ noise, const float* __restrict__ hch,
    const float* __restrict__ b1, const float* __restrict__ b2,
    const float* __restrict__ b3)
{
    extern __shared__ char smc[];
    const uint32_t sb = smem_u32(smc);
    const int t = threadIdx.x;
    const int w = t >> 5, lane = t & 31, g = lane >> 2, q = lane & 3;
    const int row0 = blockIdx.x * 64;
    float* bias = (float*)(smc + SM_BIAS);

    for (int i = t; i < 128; i += 128) bias[i]       = __ldg(b1 + i);
    if (t < 32)                        bias[128 + t] = __ldg(b2 + t);
    for (int i = t; i < 128; i += 128) bias[160 + i] = __ldg(b3 + i);

    // prologue group0: W2 + W3 + noise + W1 chunk0 ; group1: W1 chunk1
    cppad<32, 32, 576>(sb + SM_W2, gW2, t);
    cppad<128, 8, 192>(sb + SM_W3, gW3, t);
    cppad<64, 8, 144>(sb + SM_NOISE, (const unsigned char*)(noise + (size_t)row0 * 32), t);
    cppad<128, 8, 192>(sb + SM_BUF, gW1, t);
    CPCOMMIT();
    cppad<128, 8, 192>(sb + SM_BUF + SM_BUFS, gW1 + 16384, t);
    CPCOMMIT();

    const float* xrow = x + (size_t)(row0 + w * 16 + g) * 512;
    float2 xfA[8], xfB[8];
    loadx(xrow, 0, xfA, q);

    float acc[16][4];
    #pragma unroll
    for (int j = 0; j < 16; j++) { acc[j][0]=0.f; acc[j][1]=0.f; acc[j][2]=0.f; acc[j][3]=0.f; }

    // GEMM1: z1[64x128] = x @ W1^T, 16 chunks of 32 k
    for (int c = 0; c < 16; c += 2) {
        loadx(xrow, c + 1, xfB, q);
        CPWAIT1(); __syncthreads();
        compute_chunk1(smc, SM_BUF, xfA, g, q, acc);
        __syncthreads();
        if (c + 2 < 16) { cppad<128, 8, 192>(sb + SM_BUF, gW1 + (size_t)(c + 2) * 16384, t); CPCOMMIT(); }
        if (c + 2 < 16) loadx(xrow, c + 2, xfA, q);
        if (c == 14) { CPWAIT0(); } else { CPWAIT1(); }
        __syncthreads();
        compute_chunk1(smc, SM_BUF + SM_BUFS, xfB, g, q, acc);
        __syncthreads();
        if (c + 3 < 16) { cppad<128, 8, 192>(sb + SM_BUF + SM_BUFS, gW1 + (size_t)(c + 3) * 16384, t); CPCOMMIT(); }
    }

    // epilogue 1: +b1, relu, split -> chained A fragments
    uint32_t ah[8][4], al[8][4];
    #pragma unroll
    for (int j = 0; j < 16; j++) {
        float bb0 = bias[j * 8 + q * 2], bb1 = bias[j * 8 + q * 2 + 1];
        float v0 = fmaxf(acc[j][0] + bb0, 0.f), v1 = fmaxf(acc[j][1] + bb1, 0.f);
        float v2 = fmaxf(acc[j][2] + bb0, 0.f), v3 = fmaxf(acc[j][3] + bb1, 0.f);
        uint32_t h01, l01, h23, l23;
        split2(v0, v1, h01, l01);
        split2(v2, v3, h23, l23);
        int kb = j >> 1, s = (j & 1) * 2;
        ah[kb][s] = h01; ah[kb][s + 1] = h23;
        al[kb][s] = l01; al[kb][s + 1] = l23;
    }

    // GEMM2: z2[64x32] = z1 @ W2^T (K=128)
    float acc2[4][4];
    #pragma unroll
    for (int j = 0; j < 4; j++) { acc2[j][0]=0.f; acc2[j][1]=0.f; acc2[j][2]=0.f; acc2[j][3]=0.f; }
    #pragma unroll
    for (int kb = 0; kb < 8; kb++)
        gemm_step_r<4, 576>(smc, ah[kb], al[kb], SM_W2 + kb * 64, g, q, acc2);

    // epilogue 2: +b2, power-normalize, rotate, +noise (noise from smem)
    uint32_t a3h[2][4], a3l[2][4];
    {
        float vv[4][4];
        float ssg = 0.f, ssh = 0.f;
        #pragma unroll
        for (int j = 0; j < 4; j++) {
            float bb0 = bias[128 + j * 8 + q * 2], bb1 = bias[128 + j * 8 + q * 2 + 1];
            vv[j][0] = acc2[j][0] + bb0; vv[j][1] = acc2[j][1] + bb1;
            vv[j][2] = acc2[j][2] + bb0; vv[j][3] = acc2[j][3] + bb1;
            ssg += vv[j][0] * vv[j][0] + vv[j][1] * vv[j][1];
            ssh += vv[j][2] * vv[j][2] + vv[j][3] * vv[j][3];
        }
        ssg += __shfl_xor_sync(0xffffffffu, ssg, 1);
        ssg += __shfl_xor_sync(0xffffffffu, ssg, 2);
        ssh += __shfl_xor_sync(0xffffffffu, ssh, 1);
        ssh += __shfl_xor_sync(0xffffffffu, ssh, 2);
        float scg = 4.0f / sqrtf(ssg);
        float sch = 4.0f / sqrtf(ssh);
        float hc = __ldg(hch), hs = __ldg(hch + 1);
        const char* np = smc + SM_NOISE;
        int r = 16 * w + g;
        #pragma unroll
        for (int j = 0; j < 4; j++) {
            int c0 = j * 8 + q * 2;
            float2 ng = *(const float2*)(np + (size_t)r * 144 + c0 * 4);
            float2 nh = *(const float2*)(np + (size_t)(r + 8) * 144 + c0 * 4);
            float y0 = scg * (vv[j][0] * hc - vv[j][1] * hs) + ng.x;
            float y1 = scg * (vv[j][0] * hs + vv[j][1] * hc) + ng.y;
            float y2 = sch * (vv[j][2] * hc - vv[j][3] * hs) + nh.x;
            float y3 = sch * (vv[j][2] * hs + vv[j][3] * hc) + nh.y;
            uint32_t h01, l01, h23, l23;
            split2(y0, y1, h01, l01);
            split2(y2, y3, h23, l23);
            int kb = j >> 1, s = (j & 1) * 2;
            a3h[kb][s] = h01; a3h[kb][s + 1] = h23;
            a3l[kb][s] = l01; a3l[kb][s + 1] = l23;
        }
    }

    // GEMM3: d[64x128] = y @ W3^T (K=32)
    #pragma unroll
    for (int j = 0; j < 16; j++) { acc[j][0]=0.f; acc[j][1]=0.f; acc[j][2]=0.f; acc[j][3]=0.f; }
    #pragma unroll
    for (int kb = 0; kb < 2; kb++)
        gemm_step_r<16, 192>(smc, a3h[kb], a3l[kb], SM_W3 + kb * 64, g, q, acc);

    // epilogue 3: +b3, relu, split -> d-frags in gmem (A-frag layout, 512B/row)
    {
        unsigned char* dp = g_dfrag + (size_t)(row0 + 16 * w + g) * 512 + q * 16;
        #pragma unroll
        for (int kb = 0; kb < 8; kb++) {
            int je = 2 * kb, jo = 2 * kb + 1;
            float be0 = bias[160 + je * 8 + q * 2], be1 = bias[160 + je * 8 + q * 2 + 1];
            float bo0 = bias[160 + jo * 8 + q * 2], bo1 = bias[160 + jo * 8 + q * 2 + 1];
            float v0 = fmaxf(acc[je][0] + be0, 0.f), v1 = fmaxf(acc[je][1] + be1, 0.f);
            float v2 = fmaxf(acc[jo][0] + bo0, 0.f), v3 = fmaxf(acc[jo][1] + bo1, 0.f);
            uint32_t h01, l01, h23, l23;
            split2(v0, v1, h01, l01);
            split2(v2, v3, h23, l23);
            *(uint4*)(dp + kb * 64) = make_uint4(h01, h23, l01, l23);
            v0 = fmaxf(acc[je][2] + be0, 0.f); v1 = fmaxf(acc[je][3] + be1, 0.f);
            v2 = fmaxf(acc[jo][2] + bo0, 0.f); v3 = fmaxf(acc[jo][3] + bo1, 0.f);
            split2(v0, v1, h01, l01);
            split2(v2, v3, h23, l23);
            *(uint4*)(dp + 8 * 512 + kb * 64) = make_uint4(h01, h23, l01, l23);
        }
    }
}

// =============== K2: out = d @ W4^T + b4, 2D-tiled (warp = 32r x 64c) ===============
__global__ void __launch_bounds__(128, 2) gemm4_k2(
    const float* __restrict__ b4, float* __restrict__ out)
{
    extern __shared__ char smc[];
    const uint32_t sb = smem_u32(smc);
    const int t = threadIdx.x;
    const int w = t >> 5, lane = t & 31, g = lane >> 2, q = lane & 3;
    const int wm = w & 1, wn = w >> 1;           // 2 M x 2 N warps
    const int row0 = (blockIdx.x >> 2) * 64;
    const int bc = blockIdx.x & 3;               // n quarter (128 cols)

    cppad<64, 32, 576>(sb + K2_D, g_dfrag + (size_t)row0 * 512, t);
    cppad<128, 32, 576>(sb + K2_W, gW4 + (size_t)bc * 128 * 512, t);
    CPCOMMIT(); CPWAIT0();
    __syncthreads();

    float acc[2][8][4];
    #pragma unroll
    for (int mt = 0; mt < 2; mt++)
        #pragma unroll
        for (int j = 0; j < 8; j++)
            { acc[mt][j][0]=0.f; acc[mt][j][1]=0.f; acc[mt][j][2]=0.f; acc[mt][j][3]=0.f; }

    const int r0 = 32 * wm + g;
    const int nb = 64 * wn + g;
    #pragma unroll
    for (int kb = 0; kb < 8; kb++) {
        uint4 a0[2], a1[2];
        #pragma unroll
        for (int mt = 0; mt < 2; mt++) {
            a0[mt] = *(const uint4*)(smc + K2_D + (size_t)(r0 + 16 * mt) * 576 + kb * 64 + q * 16);
            a1[mt] = *(const uint4*)(smc + K2_D + (size_t)(r0 + 16 * mt + 8) * 576 + kb * 64 + q * 16);
        }
        #pragma unroll
        for (int j = 0; j < 8; j++) {
            uint4 vb = *(const uint4*)(smc + K2_W + (size_t)(nb + j * 8) * 576 + kb * 64 + q * 16);
            #pragma unroll
            for (int mt = 0; mt < 2; mt++) {
                mma16816(acc[mt][j], a0[mt].x, a1[mt].x, a0[mt].y, a1[mt].y, vb.x, vb.y);
                mma16816(acc[mt][j], a0[mt].x, a1[mt].x, a0[mt].y, a1[mt].y, vb.z, vb.w);
                mma16816(acc[mt][j], a0[mt].z, a1[mt].z, a0[mt].w, a1[mt].w, vb.x, vb.y);
            }
        }
    }

    // epilogue: +b4, store fp32
    #pragma unroll
    for (int mt = 0; mt < 2; mt++) {
        #pragma unroll
        for (int j = 0; j < 8; j++) {
            int col = bc * 128 + 64 * wn + j * 8 + q * 2;
            float bb0 = __ldg(b4 + col), bb1 = __ldg(b4 + col + 1);
            int r = row0 + 32 * wm + 16 * mt + g;
            *(float2*)(out + (size_t)r * 512 + col) =
                make_float2(acc[mt][j][0] + bb0, acc[mt][j][1] + bb1);
            *(float2*)(out + (size_t)(r + 8) * 512 + col) =
                make_float2(acc[mt][j][2] + bb0, acc[mt][j][3] + bb1);
        }
    }
}

extern "C" void kernel_launch(void* const* d_in, const int* in_sizes, int n_in,
                              void* d_out, int out_size) {
    const float* x     = (const float*)d_in[0];
    const float* noise = (const float*)d_in[1];
    const float* hch   = (const float*)d_in[2];
    const float* W1    = (const float*)d_in[3];
    const float* b1    = (const float*)d_in[4];
    const float* W2    = (const float*)d_in[5];
    const float* b2    = (const float*)d_in[6];
    const float* W3    = (const float*)d_in[7];
    const float* b3    = (const float*)d_in[8];
    const float* W4    = (const float*)d_in[9];
    const float* b4    = (const float*)d_in[10];
    float* out = (float*)d_out;

    static int configured = 0;
    if (!configured) {
        cudaFuncSetAttribute(channel_net_k1,
                             cudaFuncAttributeMaxDynamicSharedMemorySize, SM_TOTAL);
        cudaFuncSetAttribute(gemm4_k2,
                             cudaFuncAttributeMaxDynamicSharedMemorySize, K2_TOTAL);
        configured = 1;
    }
    setup_kernel<<<136, 256>>>(W1, W2, W3, W4);
    channel_net_k1<<<2048, 128, SM_TOTAL>>>(x, noise, hch, b1, b2, b3);
    gemm4_k2<<<8192, 128, K2_TOTAL>>>(b4, out);
}

// round 12
// speedup vs baseline: 1.1020x; 1.1020x over previous
#include <cuda_runtime.h>
#include <cuda_bf16.h>
#include <cstdint>

#define DINL __device__ __forceinline__

// ---------------- smem layout (bytes), per 128-thread CTA ----------------
constexpr int SM_BIAS  = 0;            // 800 floats (b1|b2|b3|b4)
constexpr int SM_W2    = 3200;         // 32 rows x stride 576   [overlaid later]
constexpr int SM_W3    = 21632;        // 128 rows x stride 192  [overlaid later]
constexpr int SM_NOISE = 46208;        // 64 rows x stride 144
constexpr int SM_BUF   = 55424;        // 2 x 24576 double buffer (W1/W4 chunks)
constexpr int SM_BUFS  = 24576;
constexpr int SM_TOTAL = SM_BUF + 2 * SM_BUFS;   // 104576 -> 2 CTAs/SM
// overlays (sequential lifetimes):
constexpr int SM_PART  = SM_W2;        // z2 partials: 2 halves x 64 rows x 136B = 17408
constexpr int SM_DEX   = SM_W2;        // d-frag exchange: 64 rows x 576B = 36864

// ---------------- preconverted weight fragments (global scratch) ----------------
// W1 chunk-major [16 chunks of 32k][128 rows][128B]; W2/W3/W4 row-major frag rows
__device__ __align__(256) unsigned char gW1[16 * 128 * 128];
__device__ __align__(256) unsigned char gW2[32 * 512];
__device__ __align__(256) unsigned char gW3[128 * 128];
__device__ __align__(256) unsigned char gW4[512 * 512];

DINL void mma16816(float c[4], uint32_t a0, uint32_t a1, uint32_t a2, uint32_t a3,
                   uint32_t b0, uint32_t b1) {
    asm volatile("mma.sync.aligned.m16n8k16.row.col.f32.bf16.bf16.f32 "
        "{%0,%1,%2,%3}, {%4,%5,%6,%7}, {%8,%9}, {%0,%1,%2,%3};"
        : "+f"(c[0]), "+f"(c[1]), "+f"(c[2]), "+f"(c[3])
        : "r"(a0), "r"(a1), "r"(a2), "r"(a3), "r"(b0), "r"(b1));
}

DINL void split2(float a, float b, uint32_t& h, uint32_t& l) {
    __nv_bfloat16 ha = __float2bfloat16(a), hb = __float2bfloat16(b);
    __nv_bfloat16 la = __float2bfloat16(a - __bfloat162float(ha));
    __nv_bfloat16 lb = __float2bfloat16(b - __bfloat162float(hb));
    h = ((uint32_t)__bfloat16_as_ushort(hb) << 16) | (uint32_t)__bfloat16_as_ushort(ha);
    l = ((uint32_t)__bfloat16_as_ushort(lb) << 16) | (uint32_t)__bfloat16_as_ushort(la);
}

// 16B frag slot at (kb,q): {h(k0,k0+1)}@0, {h(k0+8,k0+9)}@4, {l..}@8, {l..}@12
DINL void frag_store(unsigned char* p, float4 v) {
    uint32_t h0, l0, h1, l1;
    split2(v.x, v.y, h0, l0);
    split2(v.z, v.w, h1, l1);
    *(uint32_t*)(p)      = h0;
    *(uint32_t*)(p + 8)  = l0;
    *(uint32_t*)(p + 16) = h1;
    *(uint32_t*)(p + 24) = l1;
}

// ---------------- setup kernel: convert weights to fragment layout ----------------
__global__ void __launch_bounds__(256) setup_kernel(
    const float* __restrict__ W1, const float* __restrict__ W2,
    const float* __restrict__ W3, const float* __restrict__ W4)
{
    int i = blockIdx.x * 256 + threadIdx.x;
    if (i < 16384) {                       // W1 [128 x 512], 32k-chunk-major dst
        int r = i >> 7, k = (i & 127) << 2;
        float4 v = __ldg((const float4*)(W1 + (size_t)r * 512 + k));
        int c = k >> 5, kb = (k >> 4) & 1, q = (k & 7) >> 1, sub = ((k >> 3) & 1) << 2;
        frag_store(gW1 + c * 16384 + r * 128 + kb * 64 + q * 16 + sub, v);
    } else if (i < 32768) {                // W4 [512 x 128]
        int j = i - 16384;
        int r = j >> 5, k = (j & 31) << 2;
        float4 v = __ldg((const float4*)(W4 + (size_t)r * 128 + k));
        int kb = k >> 4, q = (k & 7) >> 1, sub = ((k >> 3) & 1) << 2;
        frag_store(gW4 + r * 512 + kb * 64 + q * 16 + sub, v);
    } else if (i < 33792) {                // W2 [32 x 128]
        int j = i - 32768;
        int r = j >> 5, k = (j & 31) << 2;
        float4 v = __ldg((const float4*)(W2 + (size_t)r * 128 + k));
        int kb = k >> 4, q = (k & 7) >> 1, sub = ((k >> 3) & 1) << 2;
        frag_store(gW2 + r * 512 + kb * 64 + q * 16 + sub, v);
    } else if (i < 34816) {                // W3 [128 x 32]
        int j = i - 33792;
        int r = j >> 3, k = (j & 7) << 2;
        float4 v = __ldg((const float4*)(W3 + (size_t)r * 32 + k));
        int kb = k >> 4, q = (k & 7) >> 1, sub = ((k >> 3) & 1) << 2;
        frag_store(gW3 + r * 128 + kb * 64 + q * 16 + sub, v);
    }
}

// ---------------- cp.async helpers ----------------
DINL void cpa16(uint32_t sdst, const void* gsrc) {
    asm volatile("cp.async.cg.shared.global [%0], [%1], 16;"
                 :: "r"(sdst), "l"(gsrc) : "memory");
}
#define CPCOMMIT() asm volatile("cp.async.commit_group;" ::: "memory")
#define CPWAIT1()  asm volatile("cp.async.wait_group 1;" ::: "memory")
#define CPWAIT0()  asm volatile("cp.async.wait_group 0;" ::: "memory")

DINL uint32_t smem_u32(const void* p) {
    uint32_t a;
    asm("{ .reg .u64 t; cvta.to.shared.u64 t, %1; cvt.u32.u64 %0, t; }" : "=r"(a) : "l"(p));
    return a;
}

template<int ROWS, int IPR, int RSD>
DINL void cppad(uint32_t sdst, const unsigned char* __restrict__ gsrc, int t) {
    constexpr int TOT = ROWS * IPR;
    #pragma unroll
    for (int i = t; i < TOT; i += 128) {
        int r = i / IPR, ii = i - r * IPR;
        cpa16(sdst + r * RSD + ii * 16, gsrc + (size_t)i * 16);
    }
}

// x fp32 prefetch for one 32-k chunk, 2 m-tiles (32 rows): 16 float2
DINL void loadx2(const float* __restrict__ xrow, int c, float2 xf[16], int q) {
    #pragma unroll
    for (int kb = 0; kb < 2; kb++) {
        #pragma unroll
        for (int mt = 0; mt < 2; mt++) {
            const float* p = xrow + mt * 16 * 512;
            int k0 = c * 32 + kb * 16 + q * 2;
            xf[kb * 8 + mt * 4 + 0] = __ldg((const float2*)(p + k0));
            xf[kb * 8 + mt * 4 + 1] = __ldg((const float2*)(p + 8 * 512 + k0));
            xf[kb * 8 + mt * 4 + 2] = __ldg((const float2*)(p + k0 + 8));
            xf[kb * 8 + mt * 4 + 3] = __ldg((const float2*)(p + 8 * 512 + k0 + 8));
        }
    }
}

// GEMM1 chunk compute, 2D tile: 2 kb x 8 j x 2 mt; one B LDS feeds 6 HMMAs
DINL void compute_chunk1(const char* smc, int buf, const float2 xf[16],
                         int wn, int g, int q, float acc[2][8][4]) {
    #pragma unroll
    for (int kb = 0; kb < 2; kb++) {
        uint32_t ah[2][4], al[2][4];
        #pragma unroll
        for (int mt = 0; mt < 2; mt++)
            #pragma unroll
            for (int s = 0; s < 4; s++)
                split2(xf[kb * 8 + mt * 4 + s].x, xf[kb * 8 + mt * 4 + s].y,
                       ah[mt][s], al[mt][s]);
        #pragma unroll
        for (int j = 0; j < 8; j++) {
            uint4 vb = *(const uint4*)(smc + buf +
                (size_t)(64 * wn + j * 8 + g) * 192 + kb * 64 + q * 16);
            #pragma unroll
            for (int mt = 0; mt < 2; mt++) {
                mma16816(acc[mt][j], ah[mt][0], ah[mt][1], ah[mt][2], ah[mt][3], vb.x, vb.y);
                mma16816(acc[mt][j], ah[mt][0], ah[mt][1], ah[mt][2], ah[mt][3], vb.z, vb.w);
                mma16816(acc[mt][j], al[mt][0], al[mt][1], al[mt][2], al[mt][3], vb.x, vb.y);
            }
        }
    }
}

__global__ void __launch_bounds__(128, 2) channel_net_kernel(
    const float* __restrict__ x, const float* __restrict__ noise, const float* __restrict__ hch,
    const float* __restrict__ b1, const float* __restrict__ b2,
    const float* __restrict__ b3, const float* __restrict__ b4,
    float* __restrict__ out)
{
    extern __shared__ char smc[];
    const uint32_t sb = smem_u32(smc);
    const int t = threadIdx.x;
    const int w = t >> 5, lane = t & 31, g = lane >> 2, q = lane & 3;
    const int wm = w & 1, wn = w >> 1;        // 2 M-groups x 2 N-halves
    const int row0 = blockIdx.x * 64;
    float* bias = (float*)(smc + SM_BIAS);

    for (int i = t; i < 128; i += 128) bias[i]       = __ldg(b1 + i);
    if (t < 32)                        bias[128 + t] = __ldg(b2 + t);
    for (int i = t; i < 128; i += 128) bias[160 + i] = __ldg(b3 + i);
    for (int i = t; i < 512; i += 128) bias[288 + i] = __ldg(b4 + i);

    // prologue group0: W2 + W3 + noise + W1 chunk0 ; group1: W1 chunk1
    cppad<32, 32, 576>(sb + SM_W2, gW2, t);
    cppad<128, 8, 192>(sb + SM_W3, gW3, t);
    cppad<64, 8, 144>(sb + SM_NOISE, (const unsigned char*)(noise + (size_t)row0 * 32), t);
    cppad<128, 8, 192>(sb + SM_BUF, gW1, t);
    CPCOMMIT();
    cppad<128, 8, 192>(sb + SM_BUF + SM_BUFS, gW1 + 16384, t);
    CPCOMMIT();

    const float* xrow = x + (size_t)(row0 + 32 * wm + g) * 512;
    float2 xfA[16], xfB[16];
    loadx2(xrow, 0, xfA, q);

    float acc[2][8][4];
    #pragma unroll
    for (int mt = 0; mt < 2; mt++)
        #pragma unroll
        for (int j = 0; j < 8; j++)
            { acc[mt][j][0]=0.f; acc[mt][j][1]=0.f; acc[mt][j][2]=0.f; acc[mt][j][3]=0.f; }

    // ============== GEMM1: z1[64x128] = x @ W1^T, 16 chunks of 32 k ==============
    for (int c = 0; c < 16; c += 2) {
        loadx2(xrow, c + 1, xfB, q);
        CPWAIT1(); __syncthreads();
        compute_chunk1(smc, SM_BUF, xfA, wn, g, q, acc);
        __syncthreads();
        if (c + 2 < 16) { cppad<128, 8, 192>(sb + SM_BUF, gW1 + (size_t)(c + 2) * 16384, t); CPCOMMIT(); }
        if (c + 2 < 16) loadx2(xrow, c + 2, xfA, q);
        if (c == 14) { CPWAIT0(); } else { CPWAIT1(); }
        __syncthreads();
        compute_chunk1(smc, SM_BUF + SM_BUFS, xfB, wn, g, q, acc);
        __syncthreads();
        if (c + 3 < 16) { cppad<128, 8, 192>(sb + SM_BUF + SM_BUFS, gW1 + (size_t)(c + 3) * 16384, t); CPCOMMIT(); }
    }

    // kick off W4 chunk 0/1 copies — overlap with GEMM2/3 and exchanges
    cppad<32, 32, 576>(sb + SM_BUF, gW4, t);
    CPCOMMIT();
    cppad<32, 32, 576>(sb + SM_BUF + SM_BUFS, gW4 + 32 * 512, t);
    CPCOMMIT();

    // ---- epilogue 1: +b1, relu, split -> A2 frags (rows 32wm..+32, k 64wn..+64) ----
    uint32_t a2h[4][2][4], a2l[4][2][4];
    #pragma unroll
    for (int mt = 0; mt < 2; mt++) {
        #pragma unroll
        for (int j = 0; j < 8; j++) {
            int col = 64 * wn + j * 8 + q * 2;
            float bb0 = bias[col], bb1 = bias[col + 1];
            float v0 = fmaxf(acc[mt][j][0] + bb0, 0.f), v1 = fmaxf(acc[mt][j][1] + bb1, 0.f);
            float v2 = fmaxf(acc[mt][j][2] + bb0, 0.f), v3 = fmaxf(acc[mt][j][3] + bb1, 0.f);
            uint32_t h01, l01, h23, l23;
            split2(v0, v1, h01, l01);
            split2(v2, v3, h23, l23);
            int kb = j >> 1, s = (j & 1) * 2;
            a2h[kb][mt][s] = h01; a2h[kb][mt][s + 1] = h23;
            a2l[kb][mt][s] = l01; a2l[kb][mt][s + 1] = l23;
        }
    }

    // ============== GEMM2 (split-K): partials over k in [64wn, 64wn+64) ==============
    float acc2[2][4][4];
    #pragma unroll
    for (int mt = 0; mt < 2; mt++)
        #pragma unroll
        for (int j = 0; j < 4; j++)
            { acc2[mt][j][0]=0.f; acc2[mt][j][1]=0.f; acc2[mt][j][2]=0.f; acc2[mt][j][3]=0.f; }
    #pragma unroll
    for (int kb = 0; kb < 4; kb++) {
        int kbg = 4 * wn + kb;
        #pragma unroll
        for (int j = 0; j < 4; j++) {
            uint4 vb = *(const uint4*)(smc + SM_W2 + (size_t)(j * 8 + g) * 576 + kbg * 64 + q * 16);
            #pragma unroll
            for (int mt = 0; mt < 2; mt++) {
                mma16816(acc2[mt][j], a2h[kb][mt][0], a2h[kb][mt][1], a2h[kb][mt][2], a2h[kb][mt][3], vb.x, vb.y);
                mma16816(acc2[mt][j], a2h[kb][mt][0], a2h[kb][mt][1], a2h[kb][mt][2], a2h[kb][mt][3], vb.z, vb.w);
                mma16816(acc2[mt][j], a2l[kb][mt][0], a2l[kb][mt][1], a2l[kb][mt][2], a2l[kb][mt][3], vb.x, vb.y);
            }
        }
    }
    __syncthreads();    // W2 reads done -> overlay partials onto W2 region
    {
        char* p = smc + SM_PART + wn * 8704;     // 64 rows x 136B per half
        #pragma unroll
        for (int mt = 0; mt < 2; mt++) {
            #pragma unroll
            for (int j = 0; j < 4; j++) {
                int r = 32 * wm + 16 * mt + g;
                int c0 = j * 8 + q * 2;
                *(float2*)(p + (size_t)r * 136 + c0 * 4)       = make_float2(acc2[mt][j][0], acc2[mt][j][1]);
                *(float2*)(p + (size_t)(r + 8) * 136 + c0 * 4) = make_float2(acc2[mt][j][2], acc2[mt][j][3]);
            }
        }
    }
    __syncthreads();

    // ---- epilogue 2 (owner rows 16w..+16): reduce, +b2, normalize, rotate, +noise ----
    uint32_t a3h[2][4], a3l[2][4];
    {
        const char* p0 = smc + SM_PART;
        const char* p1 = smc + SM_PART + 8704;
        int r = 16 * w + g;
        float vv[4][4];
        float ssg = 0.f, ssh = 0.f;
        #pragma unroll
        for (int j = 0; j < 4; j++) {
            int c0 = j * 8 + q * 2;
            float2 u0a = *(const float2*)(p0 + (size_t)r * 136 + c0 * 4);
            float2 u1a = *(const float2*)(p1 + (size_t)r * 136 + c0 * 4);
            float2 u0b = *(const float2*)(p0 + (size_t)(r + 8) * 136 + c0 * 4);
            float2 u1b = *(const float2*)(p1 + (size_t)(r + 8) * 136 + c0 * 4);
            float bb0 = bias[128 + c0], bb1 = bias[128 + c0 + 1];
            vv[j][0] = u0a.x + u1a.x + bb0; vv[j][1] = u0a.y + u1a.y + bb1;
            vv[j][2] = u0b.x + u1b.x + bb0; vv[j][3] = u0b.y + u1b.y + bb1;
            ssg += vv[j][0] * vv[j][0] + vv[j][1] * vv[j][1];
            ssh += vv[j][2] * vv[j][2] + vv[j][3] * vv[j][3];
        }
        ssg += __shfl_xor_sync(0xffffffffu, ssg, 1);
        ssg += __shfl_xor_sync(0xffffffffu, ssg, 2);
        ssh += __shfl_xor_sync(0xffffffffu, ssh, 1);
        ssh += __shfl_xor_sync(0xffffffffu, ssh, 2);
        float scg = 4.0f / sqrtf(ssg);       // sqrt(N*0.5) = 4
        float sch = 4.0f / sqrtf(ssh);
        float hc = __ldg(hch), hs = __ldg(hch + 1);
        const char* np = smc + SM_NOISE;
        #pragma unroll
        for (int j = 0; j < 4; j++) {
            int c0 = j * 8 + q * 2;
            float2 ng = *(const float2*)(np + (size_t)r * 144 + c0 * 4);
            float2 nh = *(const float2*)(np + (size_t)(r + 8) * 144 + c0 * 4);
            float y0 = scg * (vv[j][0] * hc - vv[j][1] * hs) + ng.x;
            float y1 = scg * (vv[j][0] * hs + vv[j][1] * hc) + ng.y;
            float y2 = sch * (vv[j][2] * hc - vv[j][3] * hs) + nh.x;
            float y3 = sch * (vv[j][2] * hs + vv[j][3] * hc) + nh.y;
            uint32_t h01, l01, h23, l23;
            split2(y0, y1, h01, l01);
            split2(y2, y3, h23, l23);
            int kb = j >> 1, s = (j & 1) * 2;
            a3h[kb][s] = h01; a3h[kb][s + 1] = h23;
            a3l[kb][s] = l01; a3l[kb][s + 1] = l23;
        }
    }

    // ============== GEMM3: d[rows 16w..+16][128] = y @ W3^T (K=32) ==============
    float acc3[16][4];
    #pragma unroll
    for (int j = 0; j < 16; j++) { acc3[j][0]=0.f; acc3[j][1]=0.f; acc3[j][2]=0.f; acc3[j][3]=0.f; }
    #pragma unroll
    for (int kb = 0; kb < 2; kb++) {
        #pragma unroll
        for (int j = 0; j < 16; j++) {
            uint4 vb = *(const uint4*)(smc + SM_W3 + (size_t)(j * 8 + g) * 192 + kb * 64 + q * 16);
            mma16816(acc3[j], a3h[kb][0], a3h[kb][1], a3h[kb][2], a3h[kb][3], vb.x, vb.y);
            mma16816(acc3[j], a3h[kb][0], a3h[kb][1], a3h[kb][2], a3h[kb][3], vb.z, vb.w);
            mma16816(acc3[j], a3l[kb][0], a3l[kb][1], a3l[kb][2], a3l[kb][3], vb.x, vb.y);
        }
    }
    __syncthreads();    // W3/partial reads done -> overlay d-frag exchange

    // ---- epilogue 3: +b3, relu, split -> d frags in smem (stride 576) ----
    {
        char* dp = smc + SM_DEX + (size_t)(16 * w + g) * 576 + q * 16;
        #pragma unroll
        for (int kb = 0; kb < 8; kb++) {
            int je = 2 * kb, jo = 2 * kb + 1;
            float be0 = bias[160 + je * 8 + q * 2], be1 = bias[160 + je * 8 + q * 2 + 1];
            float bo0 = bias[160 + jo * 8 + q * 2], bo1 = bias[160 + jo * 8 + q * 2 + 1];
            float v0 = fmaxf(acc3[je][0] + be0, 0.f), v1 = fmaxf(acc3[je][1] + be1, 0.f);
            float v2 = fmaxf(acc3[jo][0] + bo0, 0.f), v3 = fmaxf(acc3[jo][1] + bo1, 0.f);
            uint32_t h01, l01, h23, l23;
            split2(v0, v1, h01, l01);
            split2(v2, v3, h23, l23);
            *(uint4*)(dp + kb * 64) = make_uint4(h01, h23, l01, l23);
            v0 = fmaxf(acc3[je][2] + be0, 0.f); v1 = fmaxf(acc3[je][3] + be1, 0.f);
            v2 = fmaxf(acc3[jo][2] + bo0, 0.f); v3 = fmaxf(acc3[jo][3] + bo1, 0.f);
            split2(v0, v1, h01, l01);
            split2(v2, v3, h23, l23);
            *(uint4*)(dp + 8 * 576 + kb * 64) = make_uint4(h01, h23, l01, l23);
        }
    }
    __syncthreads();

    // read A4 frags: rows 32wm..+32, all 8 kb (held: 128 regs, reused 16 chunks)
    uint32_t a4h[8][2][4], a4l[8][2][4];
    #pragma unroll
    for (int kb = 0; kb < 8; kb++) {
        #pragma unroll
        for (int mt = 0; mt < 2; mt++) {
            int r = 32 * wm + 16 * mt + g;
            uint4 u0 = *(const uint4*)(smc + SM_DEX + (size_t)r * 576 + kb * 64 + q * 16);
            uint4 u1 = *(const uint4*)(smc + SM_DEX + (size_t)(r + 8) * 576 + kb * 64 + q * 16);
            a4h[kb][mt][0] = u0.x; a4h[kb][mt][1] = u1.x;
            a4h[kb][mt][2] = u0.y; a4h[kb][mt][3] = u1.y;
            a4l[kb][mt][0] = u0.z; a4l[kb][mt][1] = u1.z;
            a4l[kb][mt][2] = u0.w; a4l[kb][mt][3] = u1.w;
        }
    }

    // ============== GEMM4: out[64x512] = d @ W4^T, 16 n-chunks of 32 ==============
    for (int nc = 0; nc < 16; nc++) {
        if (nc == 15) { CPWAIT0(); } else { CPWAIT1(); }
        __syncthreads();
        int buf = SM_BUF + (nc & 1) * SM_BUFS;
        float acc4[2][2][4];
        #pragma unroll
        for (int mt = 0; mt < 2; mt++)
            #pragma unroll
            for (int j = 0; j < 2; j++)
                { acc4[mt][j][0]=0.f; acc4[mt][j][1]=0.f; acc4[mt][j][2]=0.f; acc4[mt][j][3]=0.f; }
        #pragma unroll
        for (int kb = 0; kb < 8; kb++) {
            #pragma unroll
            for (int j = 0; j < 2; j++) {
                uint4 vb = *(const uint4*)(smc + buf +
                    (size_t)(16 * wn + j * 8 + g) * 576 + kb * 64 + q * 16);
                #pragma unroll
                for (int mt = 0; mt < 2; mt++) {
                    mma16816(acc4[mt][j], a4h[kb][mt][0], a4h[kb][mt][1], a4h[kb][mt][2], a4h[kb][mt][3], vb.x, vb.y);
                    mma16816(acc4[mt][j], a4h[kb][mt][0], a4h[kb][mt][1], a4h[kb][mt][2], a4h[kb][mt][3], vb.z, vb.w);
                    mma16816(acc4[mt][j], a4l[kb][mt][0], a4l[kb][mt][1], a4l[kb][mt][2], a4l[kb][mt][3], vb.x, vb.y);
                }
            }
        }
        __syncthreads();
        if (nc + 2 < 16) {
            cppad<32, 32, 576>(sb + buf, gW4 + (size_t)(nc + 2) * 32 * 512, t);
            CPCOMMIT();
        }
        // epilogue 4: +b4, store fp32
        #pragma unroll
        for (int mt = 0; mt < 2; mt++) {
            #pragma unroll
            for (int j = 0; j < 2; j++) {
                int col = nc * 32 + 16 * wn + j * 8 + q * 2;
                float bb0 = bias[288 + col], bb1 = bias[288 + col + 1];
                int r = row0 + 32 * wm + 16 * mt + g;
                *(float2*)(out + (size_t)r * 512 + col) =
                    make_float2(acc4[mt][j][0] + bb0, acc4[mt][j][1] + bb1);
                *(float2*)(out + (size_t)(r + 8) * 512 + col) =
                    make_float2(acc4[mt][j][2] + bb0, acc4[mt][j][3] + bb1);
            }
        }
    }
}

extern "C" void kernel_launch(void* const* d_in, const int* in_sizes, int n_in,
                              void* d_out, int out_size) {
    const float* x     = (const float*)d_in[0];
    const float* noise = (const float*)d_in[1];
    const float* hch   = (const float*)d_in[2];
    const float* W1    = (const float*)d_in[3];
    const float* b1    = (const float*)d_in[4];
    const float* W2    = (const float*)d_in[5];
    const float* b2    = (const float*)d_in[6];
    const float* W3    = (const float*)d_in[7];
    const float* b3    = (const float*)d_in[8];
    const float* W4    = (const float*)d_in[9];
    const float* b4    = (const float*)d_in[10];
    float* out = (float*)d_out;

    static int configured = 0;
    if (!configured) {
        cudaFuncSetAttribute(channel_net_kernel,
                             cudaFuncAttributeMaxDynamicSharedMemorySize, SM_TOTAL);
        configured = 1;
    }
    setup_kernel<<<136, 256>>>(W1, W2, W3, W4);
    channel_net_kernel<<<2048, 128, SM_TOTAL>>>(
        x, noise, hch, b1, b2, b3, b4, out);
}

// round 13
// speedup vs baseline: 1.3569x; 1.2313x over previous
#include <cuda_runtime.h>
#include <cuda_fp16.h>
#include <cstdint>

#define DINL __device__ __forceinline__

// ---------------- smem layout (bytes), per 128-thread CTA ----------------
constexpr int SM_BIAS  = 0;            // 800 floats (b1|b2|b3|b4)
constexpr int SM_W2    = 3200;         // 32 rows x stride 576 (3-pass 16B slots)
constexpr int SM_W3    = 21632;        // 128 rows x stride 192 (3-pass)
constexpr int SM_NOISE = 46208;        // 64 rows x stride 144
constexpr int SM_BUF   = 55424;        // 2 x 18432 double buffer (hi-only W1/W4 chunks)
constexpr int SM_BUFS  = 18432;
constexpr int SM_TOTAL = SM_BUF + 2 * SM_BUFS;   // 92288 -> 2 CTAs/SM

// ---------------- preconverted fp16 weight fragments (global scratch) ----------------
// W1 hi-only, 64k-chunk-major: [8 chunks][128 rows][128B]
// W4 hi-only, row-major: [512 rows][256B]
// W2/W3 full hi+lo 16B slots: [32][512B] / [128][128B]
__device__ __align__(256) unsigned char gW1[8 * 128 * 128];
__device__ __align__(256) unsigned char gW2[32 * 512];
__device__ __align__(256) unsigned char gW3[128 * 128];
__device__ __align__(256) unsigned char gW4[512 * 256];

DINL void mma16816(float c[4], uint32_t a0, uint32_t a1, uint32_t a2, uint32_t a3,
                   uint32_t b0, uint32_t b1) {
    asm volatile("mma.sync.aligned.m16n8k16.row.col.f32.f16.f16.f32 "
        "{%0,%1,%2,%3}, {%4,%5,%6,%7}, {%8,%9}, {%0,%1,%2,%3};"
        : "+f"(c[0]), "+f"(c[1]), "+f"(c[2]), "+f"(c[3])
        : "r"(a0), "r"(a1), "r"(a2), "r"(a3), "r"(b0), "r"(b1));
}

// split fp32 pair -> packed fp16 hi (lo16 = even elem) and packed fp16 lo-residual
DINL void split2(float a, float b, uint32_t& h, uint32_t& l) {
    __half ha = __float2half_rn(a), hb = __float2half_rn(b);
    __half la = __float2half_rn(a - __half2float(ha));
    __half lb = __float2half_rn(b - __half2float(hb));
    h = ((uint32_t)__half_as_ushort(hb) << 16) | (uint32_t)__half_as_ushort(ha);
    l = ((uint32_t)__half_as_ushort(lb) << 16) | (uint32_t)__half_as_ushort(la);
}

// full 16B frag slot (hi+lo): {h0}@0, {l0}@8, {h1}@16, {l1}@24  (h1 = k+2,k+3 quad)
DINL void frag_store(unsigned char* p, float4 v) {
    uint32_t h0, l0, h1, l1;
    split2(v.x, v.y, h0, l0);
    split2(v.z, v.w, h1, l1);
    *(uint32_t*)(p)      = h0;
    *(uint32_t*)(p + 8)  = l0;
    *(uint32_t*)(p + 16) = h1;
    *(uint32_t*)(p + 24) = l1;
}

// hi-only 8B slot: {h(k0,k0+1)}@0 and next quad at +8; k+8 pairs at +4
DINL void frag_store_hi(unsigned char* p, float4 v) {
    uint32_t h0, l0, h1, l1;
    split2(v.x, v.y, h0, l0);
    split2(v.z, v.w, h1, l1);
    *(uint32_t*)(p)     = h0;
    *(uint32_t*)(p + 8) = h1;
    (void)l0; (void)l1;
}

// ---------------- setup kernel: convert weights to fp16 fragment layout ----------------
__global__ void __launch_bounds__(256) setup_kernel(
    const float* __restrict__ W1, const float* __restrict__ W2,
    const float* __restrict__ W3, const float* __restrict__ W4)
{
    int i = blockIdx.x * 256 + threadIdx.x;
    if (i < 16384) {                       // W1 [128 x 512], hi-only, 64k-chunk-major
        int r = i >> 7, k = (i & 127) << 2;
        float4 v = __ldg((const float4*)(W1 + (size_t)r * 512 + k));
        int c = k >> 6, kb = (k >> 4) & 3, q = (k & 7) >> 1, sub = ((k >> 3) & 1) << 2;
        frag_store_hi(gW1 + c * 16384 + r * 128 + kb * 32 + q * 8 + sub, v);
    } else if (i < 32768) {                // W4 [512 x 128], hi-only
        int j = i - 16384;
        int r = j >> 5, k = (j & 31) << 2;
        float4 v = __ldg((const float4*)(W4 + (size_t)r * 128 + k));
        int kb = k >> 4, q = (k & 7) >> 1, sub = ((k >> 3) & 1) << 2;
        frag_store_hi(gW4 + r * 256 + kb * 32 + q * 8 + sub, v);
    } else if (i < 33792) {                // W2 [32 x 128], full
        int j = i - 32768;
        int r = j >> 5, k = (j & 31) << 2;
        float4 v = __ldg((const float4*)(W2 + (size_t)r * 128 + k));
        int kb = k >> 4, q = (k & 7) >> 1, sub = ((k >> 3) & 1) << 2;
        frag_store(gW2 + r * 512 + kb * 64 + q * 16 + sub, v);
    } else if (i < 34816) {                // W3 [128 x 32], full
        int j = i - 33792;
        int r = j >> 3, k = (j & 7) << 2;
        float4 v = __ldg((const float4*)(W3 + (size_t)r * 32 + k));
        int kb = k >> 4, q = (k & 7) >> 1, sub = ((k >> 3) & 1) << 2;
        frag_store(gW3 + r * 128 + kb * 64 + q * 16 + sub, v);
    }
}

// ---------------- cp.async helpers ----------------
DINL void cpa16(uint32_t sdst, const void* gsrc) {
    asm volatile("cp.async.cg.shared.global [%0], [%1], 16;"
                 :: "r"(sdst), "l"(gsrc) : "memory");
}
#define CPCOMMIT() asm volatile("cp.async.commit_group;" ::: "memory")
#define CPWAIT1()  asm volatile("cp.async.wait_group 1;" ::: "memory")
#define CPWAIT0()  asm volatile("cp.async.wait_group 0;" ::: "memory")

DINL uint32_t smem_u32(const void* p) {
    uint32_t a;
    asm("{ .reg .u64 t; cvta.to.shared.u64 t, %1; cvt.u32.u64 %0, t; }" : "=r"(a) : "l"(p));
    return a;
}

// copy ROWS x (IPR*16B) contiguous gmem -> smem rows with padded stride RSD (128 thr)
template<int ROWS, int IPR, int RSD>
DINL void cppad(uint32_t sdst, const unsigned char* __restrict__ gsrc, int t) {
    constexpr int TOT = ROWS * IPR;
    #pragma unroll
    for (int i = t; i < TOT; i += 128) {
        int r = i / IPR, ii = i - r * IPR;
        cpa16(sdst + r * RSD + ii * 16, gsrc + (size_t)i * 16);
    }
}

// one 16-k step, A regs, B full 16B slots (stride RSB), NJ n-tiles, 3-pass hi/lo
template<int NJ, int RSB>
DINL void gemm_step_r(const char* smc, const uint32_t ah[4], const uint32_t al[4],
                      int boff, int g, int q, float (*acc)[4]) {
    #pragma unroll
    for (int j = 0; j < NJ; j++) {
        uint4 vb = *(const uint4*)(smc + boff + (size_t)(j * 8 + g) * RSB + q * 16);
        mma16816(acc[j], ah[0], ah[1], ah[2], ah[3], vb.x, vb.y);
        mma16816(acc[j], ah[0], ah[1], ah[2], ah[3], vb.z, vb.w);
        mma16816(acc[j], al[0], al[1], al[2], al[3], vb.x, vb.y);
    }
}

// x fp32 prefetch for one 64-k chunk: 16 float2
DINL void loadx(const float* __restrict__ xrow, int c, float2 xf[16], int q) {
    const float* p0 = xrow;              // row g
    const float* p1 = xrow + 8 * 512;    // row g+8
    #pragma unroll
    for (int kb = 0; kb < 4; kb++) {
        int k0 = c * 64 + kb * 16 + q * 2;
        xf[kb * 4 + 0] = __ldg((const float2*)(p0 + k0));
        xf[kb * 4 + 1] = __ldg((const float2*)(p1 + k0));
        xf[kb * 4 + 2] = __ldg((const float2*)(p0 + k0 + 8));
        xf[kb * 4 + 3] = __ldg((const float2*)(p1 + k0 + 8));
    }
}

// GEMM1 chunk compute: 4 kb x 16 j, 2-pass (hi-only B), B via LDS.64
DINL void compute_chunk1(const char* smc, int buf, const float2 xf[16],
                         int g, int q, float (*acc)[4]) {
    #pragma unroll
    for (int kb = 0; kb < 4; kb++) {
        uint32_t ah[4], al[4];
        #pragma unroll
        for (int s = 0; s < 4; s++)
            split2(xf[kb * 4 + s].x, xf[kb * 4 + s].y, ah[s], al[s]);
        #pragma unroll
        for (int j = 0; j < 16; j++) {
            uint2 vb = *(const uint2*)(smc + buf + (size_t)(j * 8 + g) * 144 + kb * 32 + q * 8);
            mma16816(acc[j], ah[0], ah[1], ah[2], ah[3], vb.x, vb.y);
            mma16816(acc[j], al[0], al[1], al[2], al[3], vb.x, vb.y);
        }
    }
}

__global__ void __launch_bounds__(128, 2) channel_net_kernel(
    const float* __restrict__ x, const float* __restrict__ noise, const float* __restrict__ hch,
    const float* __restrict__ b1, const float* __restrict__ b2,
    const float* __restrict__ b3, const float* __restrict__ b4,
    float* __restrict__ out)
{
    extern __shared__ char smc[];
    const uint32_t sb = smem_u32(smc);
    const int t = threadIdx.x;
    const int w = t >> 5, lane = t & 31, g = lane >> 2, q = lane & 3;
    const int row0 = blockIdx.x * 64;          // 64 rows per CTA, 4 warps x 16 rows
    float* bias = (float*)(smc + SM_BIAS);

    for (int i = t; i < 128; i += 128) bias[i]       = __ldg(b1 + i);
    if (t < 32)                        bias[128 + t] = __ldg(b2 + t);
    for (int i = t; i < 128; i += 128) bias[160 + i] = __ldg(b3 + i);
    for (int i = t; i < 512; i += 128) bias[288 + i] = __ldg(b4 + i);

    // prologue group0: W2 + W3 + noise + W1 chunk0 ; group1: W1 chunk1
    cppad<32, 32, 576>(sb + SM_W2, gW2, t);
    cppad<128, 8, 192>(sb + SM_W3, gW3, t);
    cppad<64, 8, 144>(sb + SM_NOISE, (const unsigned char*)(noise + (size_t)row0 * 32), t);
    cppad<128, 8, 144>(sb + SM_BUF, gW1, t);
    CPCOMMIT();
    cppad<128, 8, 144>(sb + SM_BUF + SM_BUFS, gW1 + 16384, t);
    CPCOMMIT();

    const float* xrow = x + (size_t)(row0 + w * 16 + g) * 512;
    float2 xfA[16], xfB[16];
    loadx(xrow, 0, xfA, q);

    float acc[16][4];
    #pragma unroll
    for (int j = 0; j < 16; j++) { acc[j][0]=0.f; acc[j][1]=0.f; acc[j][2]=0.f; acc[j][3]=0.f; }

    // ============== GEMM1: z1[64x128] = x @ W1h^T, 8 chunks of 64 k (2-pass) ==============
    for (int c = 0; c < 8; c += 2) {
        loadx(xrow, c + 1, xfB, q);
        CPWAIT1(); __syncthreads();
        compute_chunk1(smc, SM_BUF, xfA, g, q, acc);
        __syncthreads();
        if (c + 2 < 8) { cppad<128, 8, 144>(sb + SM_BUF, gW1 + (size_t)(c + 2) * 16384, t); CPCOMMIT(); }
        if (c + 2 < 8) loadx(xrow, c + 2, xfA, q);
        if (c == 6) { CPWAIT0(); } else { CPWAIT1(); }
        __syncthreads();
        compute_chunk1(smc, SM_BUF + SM_BUFS, xfB, g, q, acc);
        __syncthreads();
        if (c + 3 < 8) { cppad<128, 8, 144>(sb + SM_BUF + SM_BUFS, gW1 + (size_t)(c + 3) * 16384, t); CPCOMMIT(); }
    }

    // kick off W4 chunk 0/1 copies (hi-only, 64 cols each) — overlap with GEMM2/3
    cppad<64, 16, 272>(sb + SM_BUF, gW4, t);
    CPCOMMIT();
    cppad<64, 16, 272>(sb + SM_BUF + SM_BUFS, gW4 + 64 * 256, t);
    CPCOMMIT();

    // ---- epilogue 1: +b1, relu, split -> chained A fragments (8 kb) ----
    uint32_t ah[8][4], al[8][4];
    #pragma unroll
    for (int j = 0; j < 16; j++) {
        float bb0 = bias[j * 8 + q * 2], bb1 = bias[j * 8 + q * 2 + 1];
        float v0 = fmaxf(acc[j][0] + bb0, 0.f), v1 = fmaxf(acc[j][1] + bb1, 0.f);
        float v2 = fmaxf(acc[j][2] + bb0, 0.f), v3 = fmaxf(acc[j][3] + bb1, 0.f);
        uint32_t h01, l01, h23, l23;
        split2(v0, v1, h01, l01);
        split2(v2, v3, h23, l23);
        int kb = j >> 1, s = (j & 1) * 2;
        ah[kb][s] = h01; ah[kb][s + 1] = h23;
        al[kb][s] = l01; al[kb][s + 1] = l23;
    }

    // ============== GEMM2: z2[64x32] = z1 @ W2^T (K=128, 3-pass) ==============
    float acc2[4][4];
    #pragma unroll
    for (int j = 0; j < 4; j++) { acc2[j][0]=0.f; acc2[j][1]=0.f; acc2[j][2]=0.f; acc2[j][3]=0.f; }
    #pragma unroll
    for (int kb = 0; kb < 8; kb++)
        gemm_step_r<4, 576>(smc, ah[kb], al[kb], SM_W2 + kb * 64, g, q, acc2);

    // ---- epilogue 2: +b2, power-normalize, rotate by h, +noise (noise from smem) ----
    uint32_t a3h[2][4], a3l[2][4];
    {
        float vv[4][4];
        float ssg = 0.f, ssh = 0.f;
        #pragma unroll
        for (int j = 0; j < 4; j++) {
            float bb0 = bias[128 + j * 8 + q * 2], bb1 = bias[128 + j * 8 + q * 2 + 1];
            vv[j][0] = acc2[j][0] + bb0; vv[j][1] = acc2[j][1] + bb1;
            vv[j][2] = acc2[j][2] + bb0; vv[j][3] = acc2[j][3] + bb1;
            ssg += vv[j][0] * vv[j][0] + vv[j][1] * vv[j][1];
            ssh += vv[j][2] * vv[j][2] + vv[j][3] * vv[j][3];
        }
        ssg += __shfl_xor_sync(0xffffffffu, ssg, 1);
        ssg += __shfl_xor_sync(0xffffffffu, ssg, 2);
        ssh += __shfl_xor_sync(0xffffffffu, ssh, 1);
        ssh += __shfl_xor_sync(0xffffffffu, ssh, 2);
        float scg = 4.0f / sqrtf(ssg);       // sqrt(N*0.5) = 4
        float sch = 4.0f / sqrtf(ssh);
        float hc = __ldg(hch), hs = __ldg(hch + 1);
        const char* np = smc + SM_NOISE;
        int r = 16 * w + g;
        #pragma unroll
        for (int j = 0; j < 4; j++) {
            int c0 = j * 8 + q * 2;
            float2 ng = *(const float2*)(np + (size_t)r * 144 + c0 * 4);
            float2 nh = *(const float2*)(np + (size_t)(r + 8) * 144 + c0 * 4);
            float y0 = scg * (vv[j][0] * hc - vv[j][1] * hs) + ng.x;
            float y1 = scg * (vv[j][0] * hs + vv[j][1] * hc) + ng.y;
            float y2 = sch * (vv[j][2] * hc - vv[j][3] * hs) + nh.x;
            float y3 = sch * (vv[j][2] * hs + vv[j][3] * hc) + nh.y;
            uint32_t h01, l01, h23, l23;
            split2(y0, y1, h01, l01);
            split2(y2, y3, h23, l23);
            int kb = j >> 1, s = (j & 1) * 2;
            a3h[kb][s] = h01; a3h[kb][s + 1] = h23;
            a3l[kb][s] = l01; a3l[kb][s + 1] = l23;
        }
    }

    // ============== GEMM3: d[64x128] = y @ W3^T (K=32, 3-pass) ==============
    #pragma unroll
    for (int j = 0; j < 16; j++) { acc[j][0]=0.f; acc[j][1]=0.f; acc[j][2]=0.f; acc[j][3]=0.f; }
    #pragma unroll
    for (int kb = 0; kb < 2; kb++)
        gemm_step_r<16, 192>(smc, a3h[kb], a3l[kb], SM_W3 + kb * 64, g, q, acc);

    // ---- epilogue 3: +b3, relu, split -> A4 fragments ----
    #pragma unroll
    for (int j = 0; j < 16; j++) {
        float bb0 = bias[160 + j * 8 + q * 2], bb1 = bias[160 + j * 8 + q * 2 + 1];
        float v0 = fmaxf(acc[j][0] + bb0, 0.f), v1 = fmaxf(acc[j][1] + bb1, 0.f);
        float v2 = fmaxf(acc[j][2] + bb0, 0.f), v3 = fmaxf(acc[j][3] + bb1, 0.f);
        uint32_t h01, l01, h23, l23;
        split2(v0, v1, h01, l01);
        split2(v2, v3, h23, l23);
        int kb = j >> 1, s = (j & 1) * 2;
        ah[kb][s] = h01; ah[kb][s + 1] = h23;
        al[kb][s] = l01; al[kb][s + 1] = l23;
    }

    // ============== GEMM4: out[64x512] = d @ W4h^T, 8 n-chunks of 64 (2-pass) ==============
    for (int nc = 0; nc < 8; nc++) {
        if (nc == 7) { CPWAIT0(); } else { CPWAIT1(); }
        __syncthreads();
        int buf = SM_BUF + (nc & 1) * SM_BUFS;
        float acc4[8][4];
        #pragma unroll
        for (int j = 0; j < 8; j++) { acc4[j][0]=0.f; acc4[j][1]=0.f; acc4[j][2]=0.f; acc4[j][3]=0.f; }
        #pragma unroll
        for (int kb = 0; kb < 8; kb++) {
            #pragma unroll
            for (int j = 0; j < 8; j++) {
                uint2 vb = *(const uint2*)(smc + buf + (size_t)(j * 8 + g) * 272 + kb * 32 + q * 8);
                mma16816(acc4[j], ah[kb][0], ah[kb][1], ah[kb][2], ah[kb][3], vb.x, vb.y);
                mma16816(acc4[j], al[kb][0], al[kb][1], al[kb][2], al[kb][3], vb.x, vb.y);
            }
        }
        __syncthreads();
        if (nc + 2 < 8) {
            cppad<64, 16, 272>(sb + buf, gW4 + (size_t)(nc + 2) * 64 * 256, t);
            CPCOMMIT();
        }
        // epilogue 4: +b4, store fp32
        #pragma unroll
        for (int j = 0; j < 8; j++) {
            int col = nc * 64 + j * 8 + q * 2;
            float bb0 = bias[288 + col], bb1 = bias[288 + col + 1];
            int r = row0 + 16 * w + g;
            *(float2*)(out + (size_t)r * 512 + col) =
                make_float2(acc4[j][0] + bb0, acc4[j][1] + bb1);
            *(float2*)(out + (size_t)(r + 8) * 512 + col) =
                make_float2(acc4[j][2] + bb0, acc4[j][3] + bb1);
        }
    }
}

extern "C" void kernel_launch(void* const* d_in, const int* in_sizes, int n_in,
                              void* d_out, int out_size) {
    const float* x     = (const float*)d_in[0];
    const float* noise = (const float*)d_in[1];
    const float* hch   = (const float*)d_in[2];
    const float* W1    = (const float*)d_in[3];
    const float* b1    = (const float*)d_in[4];
    const float* W2    = (const float*)d_in[5];
    const float* b2    = (const float*)d_in[6];
    const float* W3    = (const float*)d_in[7];
    const float* b3    = (const float*)d_in[8];
    const float* W4    = (const float*)d_in[9];
    const float* b4    = (const float*)d_in[10];
    float* out = (float*)d_out;

    static int configured = 0;
    if (!configured) {
        cudaFuncSetAttribute(channel_net_kernel,
                             cudaFuncAttributeMaxDynamicSharedMemorySize, SM_TOTAL);
        configured = 1;
    }
    setup_kernel<<<136, 256>>>(W1, W2, W3, W4);
    channel_net_kernel<<<2048, 128, SM_TOTAL>>>(
        x, noise, hch, b1, b2, b3, b4, out);
}

// round 14
// speedup vs baseline: 1.5509x; 1.1430x over previous
#include <cuda_runtime.h>
#include <cuda_fp16.h>
#include <cstdint>

#define DINL __device__ __forceinline__

// ---------------- smem layout (bytes), per 128-thread CTA ----------------
constexpr int SM_BIAS  = 0;            // 800 floats (b1|b2|b3|b4)
constexpr int SM_W2    = 3200;         // 32 rows x stride 576 (3-pass 16B slots)
constexpr int SM_W3    = 21632;        // 128 rows x stride 192 (3-pass)
constexpr int SM_NOISE = 46208;        // 64 rows x stride 144
constexpr int SM_BUF   = 55424;        // 2 x 24576 double buffer
constexpr int SM_BUFS  = 24576;        // W1 chunk: 128r x 192 ; W4 chunk: 64r x 320
constexpr int SM_TOTAL = SM_BUF + 2 * SM_BUFS;   // 104576 -> 2 CTAs/SM

// ---------------- preconverted fp16 weight fragments (global scratch) ----------------
// W1 hi-only PAIRED slots, 64k-chunk-major: [8 chunks][128 rows][128B]
//   slot16(kbp,q) = {kb=2kbp 8B | kb=2kbp+1 8B}, 8B = {h(2q,2q+1)}@0 {h(2q+8,2q+9)}@4
// W4 hi-only PAIRED, row-major: [512 rows][256B] (4 kbp x 64B)
// W2/W3 full hi+lo 16B slots: [32][512B] / [128][128B]
__device__ __align__(256) unsigned char gW1[8 * 128 * 128];
__device__ __align__(256) unsigned char gW2[32 * 512];
__device__ __align__(256) unsigned char gW3[128 * 128];
__device__ __align__(256) unsigned char gW4[512 * 256];

DINL void mma16816(float c[4], uint32_t a0, uint32_t a1, uint32_t a2, uint32_t a3,
                   uint32_t b0, uint32_t b1) {
    asm volatile("mma.sync.aligned.m16n8k16.row.col.f32.f16.f16.f32 "
        "{%0,%1,%2,%3}, {%4,%5,%6,%7}, {%8,%9}, {%0,%1,%2,%3};"
        : "+f"(c[0]), "+f"(c[1]), "+f"(c[2]), "+f"(c[3])
        : "r"(a0), "r"(a1), "r"(a2), "r"(a3), "r"(b0), "r"(b1));
}

// split fp32 pair -> packed fp16 hi (lo16 = even elem) and packed fp16 lo-residual
DINL void split2(float a, float b, uint32_t& h, uint32_t& l) {
    __half ha = __float2half_rn(a), hb = __float2half_rn(b);
    __half la = __float2half_rn(a - __half2float(ha));
    __half lb = __float2half_rn(b - __half2float(hb));
    h = ((uint32_t)__half_as_ushort(hb) << 16) | (uint32_t)__half_as_ushort(ha);
    l = ((uint32_t)__half_as_ushort(lb) << 16) | (uint32_t)__half_as_ushort(la);
}

// full 16B frag slot (hi+lo): {h0}@0, {l0}@8, {h1}@16, {l1}@24  (h1 = k+2,k+3 quad)
DINL void frag_store(unsigned char* p, float4 v) {
    uint32_t h0, l0, h1, l1;
    split2(v.x, v.y, h0, l0);
    split2(v.z, v.w, h1, l1);
    *(uint32_t*)(p)      = h0;
    *(uint32_t*)(p + 8)  = l0;
    *(uint32_t*)(p + 16) = h1;
    *(uint32_t*)(p + 24) = l1;
}

// hi-only PAIRED: h0 (k,k+1) at p; h1 (k+2,k+3) at p+16 (next q slot, 16B apart)
DINL void frag_store_hi_p(unsigned char* p, float4 v) {
    uint32_t h0, l0, h1, l1;
    split2(v.x, v.y, h0, l0);
    split2(v.z, v.w, h1, l1);
    *(uint32_t*)(p)      = h0;
    *(uint32_t*)(p + 16) = h1;
    (void)l0; (void)l1;
}

// ---------------- setup kernel: convert weights to fp16 fragment layout ----------------
__global__ void __launch_bounds__(256) setup_kernel(
    const float* __restrict__ W1, const float* __restrict__ W2,
    const float* __restrict__ W3, const float* __restrict__ W4)
{
    int i = blockIdx.x * 256 + threadIdx.x;
    if (i < 16384) {                       // W1 [128 x 512], hi-only paired, 64k chunks
        int r = i >> 7, k = (i & 127) << 2;
        float4 v = __ldg((const float4*)(W1 + (size_t)r * 512 + k));
        int c = k >> 6, kb = (k >> 4) & 3, q = (k & 7) >> 1, sub = ((k >> 3) & 1) << 2;
        int kbp = kb >> 1, kbo = kb & 1;
        frag_store_hi_p(gW1 + c * 16384 + r * 128 + kbp * 64 + q * 16 + kbo * 8 + sub, v);
    } else if (i < 32768) {                // W4 [512 x 128], hi-only paired
        int j = i - 16384;
        int r = j >> 5, k = (j & 31) << 2;
        float4 v = __ldg((const float4*)(W4 + (size_t)r * 128 + k));
        int kb = k >> 4, q = (k & 7) >> 1, sub = ((k >> 3) & 1) << 2;
        int kbp = kb >> 1, kbo = kb & 1;
        frag_store_hi_p(gW4 + r * 256 + kbp * 64 + q * 16 + kbo * 8 + sub, v);
    } else if (i < 33792) {                // W2 [32 x 128], full hi+lo
        int j = i - 32768;
        int r = j >> 5, k = (j & 31) << 2;
        float4 v = __ldg((const float4*)(W2 + (size_t)r * 128 + k));
        int kb = k >> 4, q = (k & 7) >> 1, sub = ((k >> 3) & 1) << 2;
        frag_store(gW2 + r * 512 + kb * 64 + q * 16 + sub, v);
    } else if (i < 34816) {                // W3 [128 x 32], full hi+lo
        int j = i - 33792;
        int r = j >> 3, k = (j & 7) << 2;
        float4 v = __ldg((const float4*)(W3 + (size_t)r * 32 + k));
        int kb = k >> 4, q = (k & 7) >> 1, sub = ((k >> 3) & 1) << 2;
        frag_store(gW3 + r * 128 + kb * 64 + q * 16 + sub, v);
    }
}

// ---------------- cp.async helpers ----------------
DINL void cpa16(uint32_t sdst, const void* gsrc) {
    asm volatile("cp.async.cg.shared.global [%0], [%1], 16;"
                 :: "r"(sdst), "l"(gsrc) : "memory");
}
#define CPCOMMIT() asm volatile("cp.async.commit_group;" ::: "memory")
#define CPWAIT1()  asm volatile("cp.async.wait_group 1;" ::: "memory")
#define CPWAIT0()  asm volatile("cp.async.wait_group 0;" ::: "memory")

DINL uint32_t smem_u32(const void* p) {
    uint32_t a;
    asm("{ .reg .u64 t; cvta.to.shared.u64 t, %1; cvt.u32.u64 %0, t; }" : "=r"(a) : "l"(p));
    return a;
}

// copy ROWS x (IPR*16B) contiguous gmem -> smem rows with padded stride RSD (128 thr)
template<int ROWS, int IPR, int RSD>
DINL void cppad(uint32_t sdst, const unsigned char* __restrict__ gsrc, int t) {
    constexpr int TOT = ROWS * IPR;
    #pragma unroll
    for (int i = t; i < TOT; i += 128) {
        int r = i / IPR, ii = i - r * IPR;
        cpa16(sdst + r * RSD + ii * 16, gsrc + (size_t)i * 16);
    }
}

// one 16-k step, A regs, B full 16B slots (stride RSB), NJ n-tiles, 3-pass hi/lo
template<int NJ, int RSB>
DINL void gemm_step_r(const char* smc, const uint32_t ah[4], const uint32_t al[4],
                      int boff, int g, int q, float (*acc)[4]) {
    #pragma unroll
    for (int j = 0; j < NJ; j++) {
        uint4 vb = *(const uint4*)(smc + boff + (size_t)(j * 8 + g) * RSB + q * 16);
        mma16816(acc[j], ah[0], ah[1], ah[2], ah[3], vb.x, vb.y);
        mma16816(acc[j], ah[0], ah[1], ah[2], ah[3], vb.z, vb.w);
        mma16816(acc[j], al[0], al[1], al[2], al[3], vb.x, vb.y);
    }
}

// x fp32 prefetch for one 64-k chunk: 16 float2
DINL void loadx(const float* __restrict__ xrow, int c, float2 xf[16], int q) {
    const float* p0 = xrow;              // row g
    const float* p1 = xrow + 8 * 512;    // row g+8
    #pragma unroll
    for (int kb = 0; kb < 4; kb++) {
        int k0 = c * 64 + kb * 16 + q * 2;
        xf[kb * 4 + 0] = __ldg((const float2*)(p0 + k0));
        xf[kb * 4 + 1] = __ldg((const float2*)(p1 + k0));
        xf[kb * 4 + 2] = __ldg((const float2*)(p0 + k0 + 8));
        xf[kb * 4 + 3] = __ldg((const float2*)(p1 + k0 + 8));
    }
}

// GEMM1 chunk: 2 kbp x 16 j; one LDS.128 feeds 4 HMMAs (even-hi/lo, odd-hi/lo)
DINL void compute_chunk1(const char* smc, int buf, const float2 xf[16],
                         int g, int q, float (*acc)[4]) {
    #pragma unroll
    for (int kbp = 0; kbp < 2; kbp++) {
        uint32_t ahE[4], alE[4], ahO[4], alO[4];
        #pragma unroll
        for (int s = 0; s < 4; s++) {
            split2(xf[(2 * kbp) * 4 + s].x,     xf[(2 * kbp) * 4 + s].y,     ahE[s], alE[s]);
            split2(xf[(2 * kbp + 1) * 4 + s].x, xf[(2 * kbp + 1) * 4 + s].y, ahO[s], alO[s]);
        }
        #pragma unroll
        for (int j = 0; j < 16; j++) {
            uint4 vb = *(const uint4*)(smc + buf + (size_t)(j * 8 + g) * 192 + kbp * 64 + q * 16);
            mma16816(acc[j], ahE[0], ahE[1], ahE[2], ahE[3], vb.x, vb.y);
            mma16816(acc[j], alE[0], alE[1], alE[2], alE[3], vb.x, vb.y);
            mma16816(acc[j], ahO[0], ahO[1], ahO[2], ahO[3], vb.z, vb.w);
            mma16816(acc[j], alO[0], alO[1], alO[2], alO[3], vb.z, vb.w);
        }
    }
}

__global__ void __launch_bounds__(128, 2) channel_net_kernel(
    const float* __restrict__ x, const float* __restrict__ noise, const float* __restrict__ hch,
    const float* __restrict__ b1, const float* __restrict__ b2,
    const float* __restrict__ b3, const float* __restrict__ b4,
    float* __restrict__ out)
{
    extern __shared__ char smc[];
    const uint32_t sb = smem_u32(smc);
    const int t = threadIdx.x;
    const int w = t >> 5, lane = t & 31, g = lane >> 2, q = lane & 3;
    const int row0 = blockIdx.x * 64;          // 64 rows per CTA, 4 warps x 16 rows
    float* bias = (float*)(smc + SM_BIAS);

    for (int i = t; i < 128; i += 128) bias[i]       = __ldg(b1 + i);
    if (t < 32)                        bias[128 + t] = __ldg(b2 + t);
    for (int i = t; i < 128; i += 128) bias[160 + i] = __ldg(b3 + i);
    for (int i = t; i < 512; i += 128) bias[288 + i] = __ldg(b4 + i);

    // prologue group0: W2 + W3 + noise + W1 chunk0 ; group1: W1 chunk1
    cppad<32, 32, 576>(sb + SM_W2, gW2, t);
    cppad<128, 8, 192>(sb + SM_W3, gW3, t);
    cppad<64, 8, 144>(sb + SM_NOISE, (const unsigned char*)(noise + (size_t)row0 * 32), t);
    cppad<128, 8, 192>(sb + SM_BUF, gW1, t);
    CPCOMMIT();
    cppad<128, 8, 192>(sb + SM_BUF + SM_BUFS, gW1 + 16384, t);
    CPCOMMIT();

    const float* xrow = x + (size_t)(row0 + w * 16 + g) * 512;
    float2 xfA[16], xfB[16];
    loadx(xrow, 0, xfA, q);

    float acc[16][4];
    #pragma unroll
    for (int j = 0; j < 16; j++) { acc[j][0]=0.f; acc[j][1]=0.f; acc[j][2]=0.f; acc[j][3]=0.f; }

    // ============== GEMM1: z1[64x128] = x @ W1h^T, 8 chunks of 64 k (2-pass) ==============
    for (int c = 0; c < 8; c += 2) {
        loadx(xrow, c + 1, xfB, q);
        CPWAIT1(); __syncthreads();
        compute_chunk1(smc, SM_BUF, xfA, g, q, acc);
        __syncthreads();
        if (c + 2 < 8) { cppad<128, 8, 192>(sb + SM_BUF, gW1 + (size_t)(c + 2) * 16384, t); CPCOMMIT(); }
        if (c + 2 < 8) loadx(xrow, c + 2, xfA, q);
        if (c == 6) { CPWAIT0(); } else { CPWAIT1(); }
        __syncthreads();
        compute_chunk1(smc, SM_BUF + SM_BUFS, xfB, g, q, acc);
        __syncthreads();
        if (c + 3 < 8) { cppad<128, 8, 192>(sb + SM_BUF + SM_BUFS, gW1 + (size_t)(c + 3) * 16384, t); CPCOMMIT(); }
    }

    // kick off W4 chunk 0/1 copies (hi-only paired, 64 cols each) — overlap with GEMM2/3
    cppad<64, 16, 320>(sb + SM_BUF, gW4, t);
    CPCOMMIT();
    cppad<64, 16, 320>(sb + SM_BUF + SM_BUFS, gW4 + 64 * 256, t);
    CPCOMMIT();

    // ---- epilogue 1: +b1, relu, split -> chained A fragments (8 kb) ----
    uint32_t ah[8][4], al[8][4];
    #pragma unroll
    for (int j = 0; j < 16; j++) {
        float bb0 = bias[j * 8 + q * 2], bb1 = bias[j * 8 + q * 2 + 1];
        float v0 = fmaxf(acc[j][0] + bb0, 0.f), v1 = fmaxf(acc[j][1] + bb1, 0.f);
        float v2 = fmaxf(acc[j][2] + bb0, 0.f), v3 = fmaxf(acc[j][3] + bb1, 0.f);
        uint32_t h01, l01, h23, l23;
        split2(v0, v1, h01, l01);
        split2(v2, v3, h23, l23);
        int kb = j >> 1, s = (j & 1) * 2;
        ah[kb][s] = h01; ah[kb][s + 1] = h23;
        al[kb][s] = l01; al[kb][s + 1] = l23;
    }

    // ============== GEMM2: z2[64x32] = z1 @ W2^T (K=128, 3-pass) ==============
    float acc2[4][4];
    #pragma unroll
    for (int j = 0; j < 4; j++) { acc2[j][0]=0.f; acc2[j][1]=0.f; acc2[j][2]=0.f; acc2[j][3]=0.f; }
    #pragma unroll
    for (int kb = 0; kb < 8; kb++)
        gemm_step_r<4, 576>(smc, ah[kb], al[kb], SM_W2 + kb * 64, g, q, acc2);

    // ---- epilogue 2: +b2, power-normalize, rotate by h, +noise (noise from smem) ----
    uint32_t a3h[2][4], a3l[2][4];
    {
        float vv[4][4];
        float ssg = 0.f, ssh = 0.f;
        #pragma unroll
        for (int j = 0; j < 4; j++) {
            float bb0 = bias[128 + j * 8 + q * 2], bb1 = bias[128 + j * 8 + q * 2 + 1];
            vv[j][0] = acc2[j][0] + bb0; vv[j][1] = acc2[j][1] + bb1;
            vv[j][2] = acc2[j][2] + bb0; vv[j][3] = acc2[j][3] + bb1;
            ssg += vv[j][0] * vv[j][0] + vv[j][1] * vv[j][1];
            ssh += vv[j][2] * vv[j][2] + vv[j][3] * vv[j][3];
        }
        ssg += __shfl_xor_sync(0xffffffffu, ssg, 1);
        ssg += __shfl_xor_sync(0xffffffffu, ssg, 2);
        ssh += __shfl_xor_sync(0xffffffffu, ssh, 1);
        ssh += __shfl_xor_sync(0xffffffffu, ssh, 2);
        float scg = 4.0f / sqrtf(ssg);       // sqrt(N*0.5) = 4
        float sch = 4.0f / sqrtf(ssh);
        float hc = __ldg(hch), hs = __ldg(hch + 1);
        const char* np = smc + SM_NOISE;
        int r = 16 * w + g;
        #pragma unroll
        for (int j = 0; j < 4; j++) {
            int c0 = j * 8 + q * 2;
            float2 ng = *(const float2*)(np + (size_t)r * 144 + c0 * 4);
            float2 nh = *(const float2*)(np + (size_t)(r + 8) * 144 + c0 * 4);
            float y0 = scg * (vv[j][0] * hc - vv[j][1] * hs) + ng.x;
            float y1 = scg * (vv[j][0] * hs + vv[j][1] * hc) + ng.y;
            float y2 = sch * (vv[j][2] * hc - vv[j][3] * hs) + nh.x;
            float y3 = sch * (vv[j][2] * hs + vv[j][3] * hc) + nh.y;
            uint32_t h01, l01, h23, l23;
            split2(y0, y1, h01, l01);
            split2(y2, y3, h23, l23);
            int kb = j >> 1, s = (j & 1) * 2;
            a3h[kb][s] = h01; a3h[kb][s + 1] = h23;
            a3l[kb][s] = l01; a3l[kb][s + 1] = l23;
        }
    }

    // ============== GEMM3: d[64x128] = y @ W3^T (K=32, 3-pass) ==============
    #pragma unroll
    for (int j = 0; j < 16; j++) { acc[j][0]=0.f; acc[j][1]=0.f; acc[j][2]=0.f; acc[j][3]=0.f; }
    #pragma unroll
    for (int kb = 0; kb < 2; kb++)
        gemm_step_r<16, 192>(smc, a3h[kb], a3l[kb], SM_W3 + kb * 64, g, q, acc);

    // ---- epilogue 3: +b3, relu, split -> A4 fragments ----
    #pragma unroll
    for (int j = 0; j < 16; j++) {
        float bb0 = bias[160 + j * 8 + q * 2], bb1 = bias[160 + j * 8 + q * 2 + 1];
        float v0 = fmaxf(acc[j][0] + bb0, 0.f), v1 = fmaxf(acc[j][1] + bb1, 0.f);
        float v2 = fmaxf(acc[j][2] + bb0, 0.f), v3 = fmaxf(acc[j][3] + bb1, 0.f);
        uint32_t h01, l01, h23, l23;
        split2(v0, v1, h01, l01);
        split2(v2, v3, h23, l23);
        int kb = j >> 1, s = (j & 1) * 2;
        ah[kb][s] = h01; ah[kb][s + 1] = h23;
        al[kb][s] = l01; al[kb][s + 1] = l23;
    }

    // ============== GEMM4: out[64x512] = d @ W4h^T, 8 n-chunks of 64 (2-pass, paired) =====
    for (int nc = 0; nc < 8; nc++) {
        if (nc == 7) { CPWAIT0(); } else { CPWAIT1(); }
        __syncthreads();
        int buf = SM_BUF + (nc & 1) * SM_BUFS;
        float acc4[8][4];
        #pragma unroll
        for (int j = 0; j < 8; j++) { acc4[j][0]=0.f; acc4[j][1]=0.f; acc4[j][2]=0.f; acc4[j][3]=0.f; }
        #pragma unroll
        for (int kbp = 0; kbp < 4; kbp++) {
            #pragma unroll
            for (int j = 0; j < 8; j++) {
                uint4 vb = *(const uint4*)(smc + buf + (size_t)(j * 8 + g) * 320 + kbp * 64 + q * 16);
                mma16816(acc4[j], ah[2*kbp][0], ah[2*kbp][1], ah[2*kbp][2], ah[2*kbp][3], vb.x, vb.y);
                mma16816(acc4[j], al[2*kbp][0], al[2*kbp][1], al[2*kbp][2], al[2*kbp][3], vb.x, vb.y);
                mma16816(acc4[j], ah[2*kbp+1][0], ah[2*kbp+1][1], ah[2*kbp+1][2], ah[2*kbp+1][3], vb.z, vb.w);
                mma16816(acc4[j], al[2*kbp+1][0], al[2*kbp+1][1], al[2*kbp+1][2], al[2*kbp+1][3], vb.z, vb.w);
            }
        }
        __syncthreads();
        if (nc + 2 < 8) {
            cppad<64, 16, 320>(sb + buf, gW4 + (size_t)(nc + 2) * 64 * 256, t);
            CPCOMMIT();
        }
        // epilogue 4: +b4, store fp32
        #pragma unroll
        for (int j = 0; j < 8; j++) {
            int col = nc * 64 + j * 8 + q * 2;
            float bb0 = bias[288 + col], bb1 = bias[288 + col + 1];
            int r = row0 + 16 * w + g;
            *(float2*)(out + (size_t)r * 512 + col) =
                make_float2(acc4[j][0] + bb0, acc4[j][1] + bb1);
            *(float2*)(out + (size_t)(r + 8) * 512 + col) =
                make_float2(acc4[j][2] + bb0, acc4[j][3] + bb1);
        }
    }
}

extern "C" void kernel_launch(void* const* d_in, const int* in_sizes, int n_in,
                              void* d_out, int out_size) {
    const float* x     = (const float*)d_in[0];
    const float* noise = (const float*)d_in[1];
    const float* hch   = (const float*)d_in[2];
    const float* W1    = (const float*)d_in[3];
    const float* b1    = (const float*)d_in[4];
    const float* W2    = (const float*)d_in[5];
    const float* b2    = (const float*)d_in[6];
    const float* W3    = (const float*)d_in[7];
    const float* b3    = (const float*)d_in[8];
    const float* W4    = (const float*)d_in[9];
    const float* b4    = (const float*)d_in[10];
    float* out = (float*)d_out;

    static int configured = 0;
    if (!configured) {
        cudaFuncSetAttribute(channel_net_kernel,
                             cudaFuncAttributeMaxDynamicSharedMemorySize, SM_TOTAL);
        configured = 1;
    }
    setup_kernel<<<136, 256>>>(W1, W2, W3, W4);
    channel_net_kernel<<<2048, 128, SM_TOTAL>>>(
        x, noise, hch, b1, b2, b3, b4, out);
}